// round 5
// baseline (speedup 1.0000x reference)
#include <cuda_runtime.h>

// ---------------- problem constants ----------------
constexpr int B_  = 65536;
constexpr int NP  = B_ / 2;         // warp processes a pair (2p, 2p+1)
constexpr int D_  = 256;
constexpr int W1ROWS = 512, F1 = 16, W1PAD = 18;  // stride 9 words, gcd(9,16)=1 -> conflict-free LDS.64
constexpr int P1ROWS = 768, F2 = 8,  P1PAD = 10;  // stride 5 words, conflict-free

constexpr int TPB  = 192;           // 6 warps / block
constexpr int WPB  = TPB / 32;
constexpr int GRID = 296;           // 2 blocks/SM -> 12 warps/SM

// dynamic shared layout (float offsets)
constexpr int OFF_W1  = 0;                        // 512*18 = 9216
constexpr int OFF_P1  = OFF_W1 + W1ROWS * W1PAD;
constexpr int OFF_B1  = OFF_P1 + P1ROWS * P1PAD;
constexpr int OFF_W2  = OFF_B1 + 16;
constexpr int OFF_PB1 = OFF_W2 + 16;
constexpr int OFF_PW2 = OFF_PB1 + 8;
constexpr int OFF_SC  = OFF_PW2 + 8;
constexpr int SMEM_FLOATS = OFF_SC + 8;
constexpr int SMEM_BYTES  = SMEM_FLOATS * 4;      // ~67.8 KB; 2 blocks = 135.6KB/SM

// ---------------- packed f32x2 helpers ----------------
__device__ __forceinline__ unsigned long long splat2(float x) {
    unsigned long long r;
    asm("mov.b64 %0, {%1, %1};" : "=l"(r) : "f"(x));
    return r;
}
__device__ __forceinline__ void ffma2(unsigned long long& d, unsigned long long a, unsigned long long b) {
    asm("fma.rn.f32x2 %0, %1, %2, %0;" : "+l"(d) : "l"(a), "l"(b));
}
__device__ __forceinline__ float lo2(unsigned long long v) { return __uint_as_float((unsigned)v); }
__device__ __forceinline__ float hi2(unsigned long long v) { return __uint_as_float((unsigned)(v >> 32)); }

// Distributed reduce over 8 values: lane holds p[0..7] partials; returns the
// full 32-lane sum for o=(lane>>2)&7, replicated on each 4-lane o-group.
__device__ __forceinline__ float dreduce8(float* p, unsigned lane) {
    const unsigned FULL = 0xffffffffu;
    const bool b4 = (lane & 16), b3 = (lane & 8), b2 = (lane & 4);
#pragma unroll
    for (int j = 0; j < 4; j++) {
        float send = b4 ? p[j] : p[j + 4];
        float r = __shfl_xor_sync(FULL, send, 16);
        p[j] = (b4 ? p[j + 4] : p[j]) + r;
    }
#pragma unroll
    for (int j = 0; j < 2; j++) {
        float send = b3 ? p[j] : p[j + 2];
        float r = __shfl_xor_sync(FULL, send, 8);
        p[j] = (b3 ? p[j + 2] : p[j]) + r;
    }
    {
        float send = b2 ? p[0] : p[1];
        float r = __shfl_xor_sync(FULL, send, 4);
        p[0] = (b2 ? p[1] : p[0]) + r;
    }
    p[0] += __shfl_xor_sync(FULL, p[0], 2);
    p[0] += __shfl_xor_sync(FULL, p[0], 1);
    return p[0];
}

// Sum across the 8 o-groups; input identical within each 4-lane o-group.
__device__ __forceinline__ float xsum3(float v) {
    v += __shfl_xor_sync(0xffffffffu, v, 4);
    v += __shfl_xor_sync(0xffffffffu, v, 8);
    v += __shfl_xor_sync(0xffffffffu, v, 16);
    return v;
}

__global__ __launch_bounds__(TPB, 2) void agree_kernel(
    const int*   __restrict__ group_inputs,
    const int*   __restrict__ item_inputs,
    const int*   __restrict__ group_members,
    const float* __restrict__ user_emb,
    const float* __restrict__ item_emb,
    const float* __restrict__ group_emb,
    const float* __restrict__ att_w1,
    const float* __restrict__ att_b1,
    const float* __restrict__ att_w2,
    const float* __restrict__ att_b2,
    const float* __restrict__ cls_w,
    const float* __restrict__ cls_b,
    const float* __restrict__ pred_w1,
    const float* __restrict__ pred_b1,
    const float* __restrict__ pred_w2,
    const float* __restrict__ pred_b2,
    float* __restrict__ out)
{
    extern __shared__ float sm[];
    float* s_w1  = sm + OFF_W1;
    float* s_p1  = sm + OFF_P1;
    float* s_b1  = sm + OFF_B1;
    float* s_w2  = sm + OFF_W2;
    float* s_pb1 = sm + OFF_PB1;
    float* s_pw2 = sm + OFF_PW2;
    float* s_sc  = sm + OFF_SC;

    const int tid = threadIdx.x;

    for (int i = tid; i < W1ROWS * F1; i += TPB) s_w1[(i >> 4) * W1PAD + (i & 15)] = att_w1[i];
    for (int i = tid; i < P1ROWS * F2; i += TPB) s_p1[(i >> 3) * P1PAD + (i & 7)] = pred_w1[i];
    if (tid < 16) { s_b1[tid] = att_b1[tid]; s_w2[tid] = att_w2[tid]; }
    if (tid < 8)  { s_pb1[tid] = pred_b1[tid]; s_pw2[tid] = pred_w2[tid]; }
    if (tid == 0) {
        s_sc[0] = att_b2[0]; s_sc[1] = pred_b2[0];
        s_sc[2] = cls_w[0];  s_sc[3] = cls_w[1];
        s_sc[4] = cls_b[0];  s_sc[5] = cls_b[1];
    }
    __syncthreads();

    const unsigned lane = tid & 31;
    const int warp = tid >> 5;
    const int oidx = (int)((lane >> 2) & 7);
    const float b1v0 = s_b1[oidx],  b1v1 = s_b1[8 + oidx];
    const float w2v0 = s_w2[oidx],  w2v1 = s_w2[8 + oidx];
    const float pb1v = s_pb1[oidx], pw2v = s_pw2[oidx];
    const float attb2 = s_sc[0], predb2 = s_sc[1];
    const float clsd  = s_sc[3] - s_sc[2];
    const float clsbd = s_sc[5] - s_sc[4];

    const int stride = GRID * WPB;
    int p = blockIdx.x * WPB + warp;

    // ---- prologue: indices + member/item rows for first pair ----
    int b0 = 2 * p;
    int gidA = group_inputs[b0],     gidB = group_inputs[b0 + 1];
    int iidA = item_inputs[b0],      iidB = item_inputs[b0 + 1];
    int4 miA = *reinterpret_cast<const int4*>(group_members + (size_t)gidA * 4);
    int4 miB = *reinterpret_cast<const int4*>(group_members + (size_t)gidB * 4);

    float A0[8], A1[8], A2[8], A3[8], Ai[8];
    float C0[8], C1[8], C2[8], C3[8], Ci[8];   // "B" batch element
    {
        const float* a0 = user_emb + (size_t)miA.x * D_ + lane;
        const float* a1 = user_emb + (size_t)miA.y * D_ + lane;
        const float* a2 = user_emb + (size_t)miA.z * D_ + lane;
        const float* a3 = user_emb + (size_t)miA.w * D_ + lane;
        const float* ai = item_emb + (size_t)iidA  * D_ + lane;
        const float* c0 = user_emb + (size_t)miB.x * D_ + lane;
        const float* c1 = user_emb + (size_t)miB.y * D_ + lane;
        const float* c2 = user_emb + (size_t)miB.z * D_ + lane;
        const float* c3 = user_emb + (size_t)miB.w * D_ + lane;
        const float* ci = item_emb + (size_t)iidB  * D_ + lane;
#pragma unroll
        for (int k = 0; k < 8; k++) {
            A0[k] = a0[32 * k]; A1[k] = a1[32 * k]; A2[k] = a2[32 * k]; A3[k] = a3[32 * k]; Ai[k] = ai[32 * k];
            C0[k] = c0[32 * k]; C1[k] = c1[32 * k]; C2[k] = c2[32 * k]; C3[k] = c3[32 * k]; Ci[k] = ci[32 * k];
        }
    }

    while (true) {
        // group rows -> temp arrays (reused later for next-pair item prefetch)
        float tA[8], tB[8];
        {
            const float* ga = group_emb + (size_t)gidA * D_ + lane;
            const float* gb = group_emb + (size_t)gidB * D_ + lane;
#pragma unroll
            for (int k = 0; k < 8; k++) { tA[k] = ga[32 * k]; tB[k] = gb[32 * k]; }
        }

        // prefetch next pair's index chain (overlaps attention)
        const int pn = p + stride;
        const bool has_next = (pn < NP);
        int ngidA = 0, ngidB = 0, niidA = 0, niidB = 0;
        int4 nmiA = make_int4(0, 0, 0, 0), nmiB = make_int4(0, 0, 0, 0);
        if (has_next) {
            const int nb0 = 2 * pn;
            ngidA = group_inputs[nb0];     ngidB = group_inputs[nb0 + 1];
            niidA = item_inputs[nb0];      niidB = item_inputs[nb0 + 1];
            nmiA = *reinterpret_cast<const int4*>(group_members + (size_t)ngidA * 4);
            nmiB = *reinterpret_cast<const int4*>(group_members + (size_t)ngidB * 4);
        }

        // ---- attention MLP for both b's, two feature halves ----
        float lpA0 = 0.f, lpA1 = 0.f, lpA2 = 0.f, lpA3 = 0.f;
        float lpB0 = 0.f, lpB1 = 0.f, lpB2 = 0.f, lpB3 = 0.f;
#pragma unroll
        for (int H = 0; H < 2; H++) {
            unsigned long long aA0[4], aA1[4], aA2[4], aA3[4], iaA[4];
            unsigned long long aB0[4], aB1[4], aB2[4], aB3[4], iaB[4];
#pragma unroll
            for (int fp = 0; fp < 4; fp++) {
                aA0[fp] = 0; aA1[fp] = 0; aA2[fp] = 0; aA3[fp] = 0; iaA[fp] = 0;
                aB0[fp] = 0; aB1[fp] = 0; aB2[fp] = 0; aB3[fp] = 0; iaB[fp] = 0;
            }
#pragma unroll
            for (int k = 0; k < 8; k++) {
                const int e = (int)lane + 32 * k;
                const float* wr  = s_w1 + e * W1PAD + 8 * H;
                const float* wr2 = wr + 256 * W1PAD;
                const unsigned long long vA0 = splat2(A0[k]);
                const unsigned long long vA1 = splat2(A1[k]);
                const unsigned long long vA2 = splat2(A2[k]);
                const unsigned long long vA3 = splat2(A3[k]);
                const unsigned long long vAi = splat2(Ai[k]);
                const unsigned long long vB0 = splat2(C0[k]);
                const unsigned long long vB1 = splat2(C1[k]);
                const unsigned long long vB2 = splat2(C2[k]);
                const unsigned long long vB3 = splat2(C3[k]);
                const unsigned long long vBi = splat2(Ci[k]);
#pragma unroll
                for (int fp = 0; fp < 4; fp++) {
                    const unsigned long long w = *reinterpret_cast<const unsigned long long*>(wr + 2 * fp);
                    ffma2(aA0[fp], vA0, w); ffma2(aA1[fp], vA1, w);
                    ffma2(aA2[fp], vA2, w); ffma2(aA3[fp], vA3, w);
                    ffma2(aB0[fp], vB0, w); ffma2(aB1[fp], vB1, w);
                    ffma2(aB2[fp], vB2, w); ffma2(aB3[fp], vB3, w);
                    const unsigned long long wI = *reinterpret_cast<const unsigned long long*>(wr2 + 2 * fp);
                    ffma2(iaA[fp], vAi, wI); ffma2(iaB[fp], vBi, wI);
                }
            }
            const float b1v = H ? b1v1 : b1v0;
            const float w2v = H ? w2v1 : w2v0;
#define ATT_RED(acc, ia, lp)                                          \
            {                                                         \
                float pp[8];                                          \
                _Pragma("unroll")                                     \
                for (int fp = 0; fp < 4; fp++) {                      \
                    pp[2 * fp]     = lo2(acc[fp]) + lo2(ia[fp]);      \
                    pp[2 * fp + 1] = hi2(acc[fp]) + hi2(ia[fp]);      \
                }                                                     \
                const float hs = dreduce8(pp, lane);                  \
                lp += fmaxf(hs + b1v, 0.0f) * w2v;                    \
            }
            ATT_RED(aA0, iaA, lpA0) ATT_RED(aA1, iaA, lpA1)
            ATT_RED(aA2, iaA, lpA2) ATT_RED(aA3, iaA, lpA3)
            ATT_RED(aB0, iaB, lpB0) ATT_RED(aB1, iaB, lpB1)
            ATT_RED(aB2, iaB, lpB2) ATT_RED(aB3, iaB, lpB3)
#undef ATT_RED
        }

        // softmax + argmax + class + g, per batch element
        float wA0, wA1, wA2, wA3, wB0v, wB1v, wB2v, wB3v;
        bool pcA, pcB;
        float gA[8], gB[8];
        {
            float l0 = xsum3(lpA0) + attb2, l1 = xsum3(lpA1) + attb2;
            float l2 = xsum3(lpA2) + attb2, l3 = xsum3(lpA3) + attb2;
            float mx = l0; int mi = 0;
            if (l1 > mx) { mx = l1; mi = 1; }
            if (l2 > mx) { mx = l2; mi = 2; }
            if (l3 > mx) { mx = l3; mi = 3; }
            const float e0 = __expf(l0 - mx), e1 = __expf(l1 - mx);
            const float e2 = __expf(l2 - mx), e3 = __expf(l3 - mx);
            const float inv = 1.0f / (e0 + e1 + e2 + e3);
            wA0 = e0 * inv; wA1 = e1 * inv; wA2 = e2 * inv; wA3 = e3 * inv;
            const float wmx = (mi == 0) ? wA0 : (mi == 1) ? wA1 : (mi == 2) ? wA2 : wA3;
            pcA = (wmx * clsd + clsbd) > 0.0f;
#pragma unroll
            for (int k = 0; k < 8; k++) {
                const float ws = wA0 * A0[k] + wA1 * A1[k] + wA2 * A2[k] + wA3 * A3[k];
                const float ld = (mi == 0) ? A0[k] : (mi == 1) ? A1[k] : (mi == 2) ? A2[k] : A3[k];
                gA[k] = (pcA ? ld : ws) + tA[k];
            }
        }
        {
            float l0 = xsum3(lpB0) + attb2, l1 = xsum3(lpB1) + attb2;
            float l2 = xsum3(lpB2) + attb2, l3 = xsum3(lpB3) + attb2;
            float mx = l0; int mi = 0;
            if (l1 > mx) { mx = l1; mi = 1; }
            if (l2 > mx) { mx = l2; mi = 2; }
            if (l3 > mx) { mx = l3; mi = 3; }
            const float e0 = __expf(l0 - mx), e1 = __expf(l1 - mx);
            const float e2 = __expf(l2 - mx), e3 = __expf(l3 - mx);
            const float inv = 1.0f / (e0 + e1 + e2 + e3);
            wB0v = e0 * inv; wB1v = e1 * inv; wB2v = e2 * inv; wB3v = e3 * inv;
            const float wmx = (mi == 0) ? wB0v : (mi == 1) ? wB1v : (mi == 2) ? wB2v : wB3v;
            pcB = (wmx * clsd + clsbd) > 0.0f;
#pragma unroll
            for (int k = 0; k < 8; k++) {
                const float ws = wB0v * C0[k] + wB1v * C1[k] + wB2v * C2[k] + wB3v * C3[k];
                const float ld = (mi == 0) ? C0[k] : (mi == 1) ? C1[k] : (mi == 2) ? C2[k] : C3[k];
                gB[k] = (pcB ? ld : ws) + tB[k];
            }
        }

        // ---- prefetch next pair's rows (member arrays dead; items -> tA/tB) ----
        if (has_next) {
            const float* a0 = user_emb + (size_t)nmiA.x * D_ + lane;
            const float* a1 = user_emb + (size_t)nmiA.y * D_ + lane;
            const float* a2 = user_emb + (size_t)nmiA.z * D_ + lane;
            const float* a3 = user_emb + (size_t)nmiA.w * D_ + lane;
            const float* ai = item_emb + (size_t)niidA  * D_ + lane;
            const float* c0 = user_emb + (size_t)nmiB.x * D_ + lane;
            const float* c1 = user_emb + (size_t)nmiB.y * D_ + lane;
            const float* c2 = user_emb + (size_t)nmiB.z * D_ + lane;
            const float* c3 = user_emb + (size_t)nmiB.w * D_ + lane;
            const float* ci = item_emb + (size_t)niidB  * D_ + lane;
#pragma unroll
            for (int k = 0; k < 8; k++) {
                A0[k] = a0[32 * k]; A1[k] = a1[32 * k]; A2[k] = a2[32 * k]; A3[k] = a3[32 * k];
                C0[k] = c0[32 * k]; C1[k] = c1[32 * k]; C2[k] = c2[32 * k]; C3[k] = c3[32 * k];
                tA[k] = ai[32 * k]; tB[k] = ci[32 * k];
            }
        }

        // ---- prediction MLP for both b's (weights shared) ----
        unsigned long long paA[4] = {0, 0, 0, 0}, paB[4] = {0, 0, 0, 0};
#pragma unroll
        for (int k = 0; k < 8; k++) {
            const int e = (int)lane + 32 * k;
            const float* r0 = s_p1 + e * P1PAD;
            const float* r1 = r0 + 256 * P1PAD;
            const float* r2 = r1 + 256 * P1PAD;
            const unsigned long long veA = splat2(gA[k] * Ai[k]);
            const unsigned long long vgA = splat2(gA[k]);
            const unsigned long long viA = splat2(Ai[k]);
            const unsigned long long veB = splat2(gB[k] * Ci[k]);
            const unsigned long long vgB = splat2(gB[k]);
            const unsigned long long viB = splat2(Ci[k]);
#pragma unroll
            for (int op = 0; op < 4; op++) {
                const unsigned long long w0 = *reinterpret_cast<const unsigned long long*>(r0 + 2 * op);
                ffma2(paA[op], veA, w0); ffma2(paB[op], veB, w0);
                const unsigned long long w1 = *reinterpret_cast<const unsigned long long*>(r1 + 2 * op);
                ffma2(paA[op], vgA, w1); ffma2(paB[op], vgB, w1);
                const unsigned long long w2 = *reinterpret_cast<const unsigned long long*>(r2 + 2 * op);
                ffma2(paA[op], viA, w2); ffma2(paB[op], viB, w2);
            }
        }
        float yA, yB;
        {
            float q[8];
#pragma unroll
            for (int op = 0; op < 4; op++) { q[2 * op] = lo2(paA[op]); q[2 * op + 1] = hi2(paA[op]); }
            const float ps = dreduce8(q, lane);
            const float h2 = fmaxf(ps + pb1v, 0.0f);
            const float z = xsum3(h2 * pw2v) + predb2;
            yA = 1.0f / (1.0f + __expf(-z));
        }
        {
            float q[8];
#pragma unroll
            for (int op = 0; op < 4; op++) { q[2 * op] = lo2(paB[op]); q[2 * op + 1] = hi2(paB[op]); }
            const float ps = dreduce8(q, lane);
            const float h2 = fmaxf(ps + pb1v, 0.0f);
            const float z = xsum3(h2 * pw2v) + predb2;
            yB = 1.0f / (1.0f + __expf(-z));
        }

        if (lane == 0) {
            out[b0] = yA;           out[b0 + 1] = yB;
            out[5 * B_ + b0] = pcA ? 1.0f : 0.0f;
            out[5 * B_ + b0 + 1] = pcB ? 1.0f : 0.0f;
        }
        if (lane < 8) {
            const float w = (lane == 0) ? wA0 : (lane == 1) ? wA1 : (lane == 2) ? wA2 : (lane == 3) ? wA3
                          : (lane == 4) ? wB0v : (lane == 5) ? wB1v : (lane == 6) ? wB2v : wB3v;
            out[B_ + 4 * b0 + (int)lane] = w;
        }

        if (!has_next) break;
#pragma unroll
        for (int k = 0; k < 8; k++) { Ai[k] = tA[k]; Ci[k] = tB[k]; }
        gidA = ngidA; gidB = ngidB; iidA = niidA; iidB = niidB;
        p = pn; b0 = 2 * p;
    }
}

extern "C" void kernel_launch(void* const* d_in, const int* in_sizes, int n_in,
                              void* d_out, int out_size) {
    cudaFuncSetAttribute(agree_kernel, cudaFuncAttributeMaxDynamicSharedMemorySize, SMEM_BYTES);
    agree_kernel<<<GRID, TPB, SMEM_BYTES>>>(
        (const int*)d_in[0], (const int*)d_in[1], (const int*)d_in[2],
        (const float*)d_in[3], (const float*)d_in[4], (const float*)d_in[5],
        (const float*)d_in[6], (const float*)d_in[7], (const float*)d_in[8], (const float*)d_in[9],
        (const float*)d_in[10], (const float*)d_in[11], (const float*)d_in[12], (const float*)d_in[13],
        (const float*)d_in[14], (const float*)d_in[15],
        (float*)d_out);
}

// round 6
// speedup vs baseline: 1.3718x; 1.3718x over previous
#include <cuda_runtime.h>

// ---------------- problem constants ----------------
constexpr int B_  = 65536;
constexpr int D_  = 256;
constexpr int W1ROWS = 512, F1 = 16, W1PAD = 20;  // 80B rows: LDS.128-aligned, 5-unit stride, gcd(5,8)=1 -> conflict-free
constexpr int P1ROWS = 768, F2 = 8,  P1PAD = 12;  // 48B rows: 3-unit stride, gcd(3,8)=1 -> conflict-free

constexpr int TPB  = 256;           // 8 warps / block
constexpr int WPB  = TPB / 32;
constexpr int GRID = 296;           // 2 blocks/SM -> 16 warps/SM

// dynamic shared layout (float offsets)
constexpr int OFF_W1  = 0;                        // 512*20 = 10240
constexpr int OFF_P1  = OFF_W1 + W1ROWS * W1PAD;  // 10240
constexpr int OFF_B1  = OFF_P1 + P1ROWS * P1PAD;  // +9216 = 19456
constexpr int OFF_W2  = OFF_B1 + 16;
constexpr int OFF_PB1 = OFF_W2 + 16;
constexpr int OFF_PW2 = OFF_PB1 + 8;
constexpr int OFF_SC  = OFF_PW2 + 8;
constexpr int SMEM_FLOATS = OFF_SC + 8;           // 19512
constexpr int SMEM_BYTES  = SMEM_FLOATS * 4;      // ~78.0 KB; 2 blocks = 156KB/SM

// ---------------- packed f32x2 helpers ----------------
__device__ __forceinline__ unsigned long long splat2(float x) {
    unsigned long long r;
    asm("mov.b64 %0, {%1, %1};" : "=l"(r) : "f"(x));
    return r;
}
__device__ __forceinline__ unsigned long long pack2(unsigned x, unsigned y) {
    unsigned long long r;
    asm("mov.b64 %0, {%1, %2};" : "=l"(r) : "r"(x), "r"(y));
    return r;
}
__device__ __forceinline__ void ffma2(unsigned long long& d, unsigned long long a, unsigned long long b) {
    asm("fma.rn.f32x2 %0, %1, %2, %0;" : "+l"(d) : "l"(a), "l"(b));
}
__device__ __forceinline__ float lo2(unsigned long long v) { return __uint_as_float((unsigned)v); }
__device__ __forceinline__ float hi2(unsigned long long v) { return __uint_as_float((unsigned)(v >> 32)); }

// Distributed reduce over 8 values: lane holds p[0..7] partials; returns the
// full 32-lane sum for o=(lane>>2)&7, replicated on each 4-lane o-group.
__device__ __forceinline__ float dreduce8(float* p, unsigned lane) {
    const unsigned FULL = 0xffffffffu;
    const bool b4 = (lane & 16), b3 = (lane & 8), b2 = (lane & 4);
#pragma unroll
    for (int j = 0; j < 4; j++) {
        float send = b4 ? p[j] : p[j + 4];
        float r = __shfl_xor_sync(FULL, send, 16);
        p[j] = (b4 ? p[j + 4] : p[j]) + r;
    }
#pragma unroll
    for (int j = 0; j < 2; j++) {
        float send = b3 ? p[j] : p[j + 2];
        float r = __shfl_xor_sync(FULL, send, 8);
        p[j] = (b3 ? p[j + 2] : p[j]) + r;
    }
    {
        float send = b2 ? p[0] : p[1];
        float r = __shfl_xor_sync(FULL, send, 4);
        p[0] = (b2 ? p[1] : p[0]) + r;
    }
    p[0] += __shfl_xor_sync(FULL, p[0], 2);
    p[0] += __shfl_xor_sync(FULL, p[0], 1);
    return p[0];
}

// Sum across the 8 o-groups; input identical within each 4-lane o-group.
__device__ __forceinline__ float xsum3(float v) {
    v += __shfl_xor_sync(0xffffffffu, v, 4);
    v += __shfl_xor_sync(0xffffffffu, v, 8);
    v += __shfl_xor_sync(0xffffffffu, v, 16);
    return v;
}

__global__ __launch_bounds__(TPB, 2) void agree_kernel(
    const int*   __restrict__ group_inputs,
    const int*   __restrict__ item_inputs,
    const int*   __restrict__ group_members,
    const float* __restrict__ user_emb,
    const float* __restrict__ item_emb,
    const float* __restrict__ group_emb,
    const float* __restrict__ att_w1,
    const float* __restrict__ att_b1,
    const float* __restrict__ att_w2,
    const float* __restrict__ att_b2,
    const float* __restrict__ cls_w,
    const float* __restrict__ cls_b,
    const float* __restrict__ pred_w1,
    const float* __restrict__ pred_b1,
    const float* __restrict__ pred_w2,
    const float* __restrict__ pred_b2,
    float* __restrict__ out)
{
    extern __shared__ float sm[];
    float* s_w1  = sm + OFF_W1;
    float* s_p1  = sm + OFF_P1;
    float* s_b1  = sm + OFF_B1;
    float* s_w2  = sm + OFF_W2;
    float* s_pb1 = sm + OFF_PB1;
    float* s_pw2 = sm + OFF_PW2;
    float* s_sc  = sm + OFF_SC;

    const int tid = threadIdx.x;

    // stage weights (padded rows: 16B-aligned + phase-conflict-free for LDS.128)
    for (int i = tid; i < W1ROWS * F1; i += TPB) s_w1[(i >> 4) * W1PAD + (i & 15)] = att_w1[i];
    for (int i = tid; i < P1ROWS * F2; i += TPB) s_p1[(i >> 3) * P1PAD + (i & 7)] = pred_w1[i];
    if (tid < 16) { s_b1[tid] = att_b1[tid]; s_w2[tid] = att_w2[tid]; }
    if (tid < 8)  { s_pb1[tid] = pred_b1[tid]; s_pw2[tid] = pred_w2[tid]; }
    if (tid == 0) {
        s_sc[0] = att_b2[0]; s_sc[1] = pred_b2[0];
        s_sc[2] = cls_w[0];  s_sc[3] = cls_w[1];
        s_sc[4] = cls_b[0];  s_sc[5] = cls_b[1];
    }
    __syncthreads();

    const unsigned lane = tid & 31;
    const int warp = tid >> 5;
    const int oidx = (int)((lane >> 2) & 7);
    const float b1v0 = s_b1[oidx],  b1v1 = s_b1[8 + oidx];
    const float w2v0 = s_w2[oidx],  w2v1 = s_w2[8 + oidx];
    const float pb1v = s_pb1[oidx], pw2v = s_pw2[oidx];
    const float attb2 = s_sc[0], predb2 = s_sc[1];
    const float clsd  = s_sc[3] - s_sc[2];
    const float clsbd = s_sc[5] - s_sc[4];

    const int stride = GRID * WPB;
    int b = blockIdx.x * WPB + warp;

    // ---- pipeline prologue: indices + member/item rows for first b ----
    int gid = group_inputs[b];
    int iid = item_inputs[b];
    int4 mi4 = *reinterpret_cast<const int4*>(group_members + (size_t)gid * 4);

    float m0[8], m1[8], m2[8], m3[8], it[8];
    {
        const float* u0 = user_emb + (size_t)mi4.x * D_ + lane;
        const float* u1 = user_emb + (size_t)mi4.y * D_ + lane;
        const float* u2 = user_emb + (size_t)mi4.z * D_ + lane;
        const float* u3 = user_emb + (size_t)mi4.w * D_ + lane;
        const float* ip = item_emb + (size_t)iid   * D_ + lane;
#pragma unroll
        for (int k = 0; k < 8; k++) {
            m0[k] = u0[32 * k]; m1[k] = u1[32 * k];
            m2[k] = u2[32 * k]; m3[k] = u3[32 * k];
            it[k] = ip[32 * k];
        }
    }

    while (true) {
        // group-row load issued early (latency covered by attention phase)
        const float* gep = group_emb + (size_t)gid * D_ + lane;
        float ge[8];
#pragma unroll
        for (int k = 0; k < 8; k++) ge[k] = gep[32 * k];

        // prefetch next-b index chain (overlaps attention FFMA phase)
        const int bn = b + stride;
        const bool has_next = (bn < B_);
        int ngid = 0, niid = 0;
        int4 nmi4 = make_int4(0, 0, 0, 0);
        if (has_next) {
            ngid = group_inputs[bn];
            niid = item_inputs[bn];
            nmi4 = *reinterpret_cast<const int4*>(group_members + (size_t)ngid * 4);
        }

        // ---- attention MLP in two feature halves (f = 8H + [0,8)) ----
        float lp0 = 0.f, lp1 = 0.f, lp2 = 0.f, lp3 = 0.f;
#pragma unroll
        for (int H = 0; H < 2; H++) {
            unsigned long long a0[4], a1[4], a2[4], a3[4], ia[4];
#pragma unroll
            for (int fp = 0; fp < 4; fp++) { a0[fp] = 0; a1[fp] = 0; a2[fp] = 0; a3[fp] = 0; ia[fp] = 0; }
#pragma unroll
            for (int k = 0; k < 8; k++) {
                const int e = (int)lane + 32 * k;
                const float* wr  = s_w1 + e * W1PAD + 8 * H;   // member half rows [0,256)
                const float* wr2 = wr + 256 * W1PAD;           // item half rows [256,512)
                // 8 weight floats per row segment via 2x LDS.128
                const uint4 q0 = *reinterpret_cast<const uint4*>(wr);
                const uint4 q1 = *reinterpret_cast<const uint4*>(wr + 4);
                const uint4 r0 = *reinterpret_cast<const uint4*>(wr2);
                const uint4 r1 = *reinterpret_cast<const uint4*>(wr2 + 4);
                unsigned long long w[4], wI[4];
                w[0]  = pack2(q0.x, q0.y); w[1]  = pack2(q0.z, q0.w);
                w[2]  = pack2(q1.x, q1.y); w[3]  = pack2(q1.z, q1.w);
                wI[0] = pack2(r0.x, r0.y); wI[1] = pack2(r0.z, r0.w);
                wI[2] = pack2(r1.x, r1.y); wI[3] = pack2(r1.z, r1.w);
                const unsigned long long v0 = splat2(m0[k]);
                const unsigned long long v1 = splat2(m1[k]);
                const unsigned long long v2 = splat2(m2[k]);
                const unsigned long long v3 = splat2(m3[k]);
                const unsigned long long vi = splat2(it[k]);
#pragma unroll
                for (int fp = 0; fp < 4; fp++) {
                    ffma2(a0[fp], v0, w[fp]);
                    ffma2(a1[fp], v1, w[fp]);
                    ffma2(a2[fp], v2, w[fp]);
                    ffma2(a3[fp], v3, w[fp]);
                    ffma2(ia[fp], vi, wI[fp]);
                }
            }
            const float b1v = H ? b1v1 : b1v0;
            const float w2v = H ? w2v1 : w2v0;
#pragma unroll
            for (int s = 0; s < 4; s++) {
                const unsigned long long* a = (s == 0) ? a0 : (s == 1) ? a1 : (s == 2) ? a2 : a3;
                float p[8];
#pragma unroll
                for (int fp = 0; fp < 4; fp++) {
                    p[2 * fp]     = lo2(a[fp]) + lo2(ia[fp]);
                    p[2 * fp + 1] = hi2(a[fp]) + hi2(ia[fp]);
                }
                const float hs = dreduce8(p, lane);
                const float h = fmaxf(hs + b1v, 0.0f);
                const float c = h * w2v;
                if      (s == 0) lp0 += c;
                else if (s == 1) lp1 += c;
                else if (s == 2) lp2 += c;
                else             lp3 += c;
            }
        }
        float logits[4];
        logits[0] = xsum3(lp0) + attb2;
        logits[1] = xsum3(lp1) + attb2;
        logits[2] = xsum3(lp2) + attb2;
        logits[3] = xsum3(lp3) + attb2;

        // softmax + first-argmax (strict > matches jnp.argmax tie rule)
        float mx = logits[0]; int mi = 0;
#pragma unroll
        for (int s = 1; s < 4; s++) if (logits[s] > mx) { mx = logits[s]; mi = s; }
        const float e0 = __expf(logits[0] - mx), e1 = __expf(logits[1] - mx);
        const float e2 = __expf(logits[2] - mx), e3 = __expf(logits[3] - mx);
        const float inv = 1.0f / (e0 + e1 + e2 + e3);
        const float wt0 = e0 * inv, wt1 = e1 * inv, wt2 = e2 * inv, wt3 = e3 * inv;
        const float wmx = (mi == 0) ? wt0 : (mi == 1) ? wt1 : (mi == 2) ? wt2 : wt3;
        const bool pc = (wmx * clsd + clsbd) > 0.0f;

        // g = (leader | weighted) + group_emb  (last use of m0..m3)
        float g[8];
#pragma unroll
        for (int k = 0; k < 8; k++) {
            const float ws = wt0 * m0[k] + wt1 * m1[k] + wt2 * m2[k] + wt3 * m3[k];
            const float ld = (mi == 0) ? m0[k] : (mi == 1) ? m1[k] : (mi == 2) ? m2[k] : m3[k];
            g[k] = (pc ? ld : ws) + ge[k];
        }

        // ---- issue next-b row loads NOW (m regs dead; overlaps pred MLP) ----
        float nit[8];
        if (has_next) {
            const float* u0 = user_emb + (size_t)nmi4.x * D_ + lane;
            const float* u1 = user_emb + (size_t)nmi4.y * D_ + lane;
            const float* u2 = user_emb + (size_t)nmi4.z * D_ + lane;
            const float* u3 = user_emb + (size_t)nmi4.w * D_ + lane;
            const float* ip = item_emb + (size_t)niid   * D_ + lane;
#pragma unroll
            for (int k = 0; k < 8; k++) {
                m0[k] = u0[32 * k]; m1[k] = u1[32 * k];
                m2[k] = u2[32 * k]; m3[k] = u3[32 * k];
                nit[k] = ip[32 * k];
            }
        }

        // ---- prediction MLP: sigmoid(relu([g*it, g, it] @ pred_w1 + b1) @ pred_w2 + b2) ----
        unsigned long long pa[4] = {0, 0, 0, 0};
#pragma unroll
        for (int k = 0; k < 8; k++) {
            const int e = (int)lane + 32 * k;
            const float* r0 = s_p1 + e * P1PAD;       // elem rows [0,256)
            const float* r1 = r0 + 256 * P1PAD;       // g rows    [256,512)
            const float* r2 = r1 + 256 * P1PAD;       // item rows [512,768)
            const uint4 qa0 = *reinterpret_cast<const uint4*>(r0);
            const uint4 qa1 = *reinterpret_cast<const uint4*>(r0 + 4);
            const uint4 qb0 = *reinterpret_cast<const uint4*>(r1);
            const uint4 qb1 = *reinterpret_cast<const uint4*>(r1 + 4);
            const uint4 qc0 = *reinterpret_cast<const uint4*>(r2);
            const uint4 qc1 = *reinterpret_cast<const uint4*>(r2 + 4);
            unsigned long long we[4], wg[4], wi[4];
            we[0] = pack2(qa0.x, qa0.y); we[1] = pack2(qa0.z, qa0.w);
            we[2] = pack2(qa1.x, qa1.y); we[3] = pack2(qa1.z, qa1.w);
            wg[0] = pack2(qb0.x, qb0.y); wg[1] = pack2(qb0.z, qb0.w);
            wg[2] = pack2(qb1.x, qb1.y); wg[3] = pack2(qb1.z, qb1.w);
            wi[0] = pack2(qc0.x, qc0.y); wi[1] = pack2(qc0.z, qc0.w);
            wi[2] = pack2(qc1.x, qc1.y); wi[3] = pack2(qc1.z, qc1.w);
            const unsigned long long ve = splat2(g[k] * it[k]);
            const unsigned long long vg = splat2(g[k]);
            const unsigned long long vi = splat2(it[k]);
#pragma unroll
            for (int op = 0; op < 4; op++) {
                ffma2(pa[op], ve, we[op]);
                ffma2(pa[op], vg, wg[op]);
                ffma2(pa[op], vi, wi[op]);
            }
        }
        float q[8];
#pragma unroll
        for (int op = 0; op < 4; op++) { q[2 * op] = lo2(pa[op]); q[2 * op + 1] = hi2(pa[op]); }
        const float ps = dreduce8(q, lane);
        const float h2 = fmaxf(ps + pb1v, 0.0f);
        const float z = xsum3(h2 * pw2v) + predb2;
        const float y = 1.0f / (1.0f + __expf(-z));

        if (lane == 0) {
            out[b] = y;
            out[5 * B_ + b] = pc ? 1.0f : 0.0f;
        }
        if (lane < 4) {
            const float w = (lane == 0) ? wt0 : (lane == 1) ? wt1 : (lane == 2) ? wt2 : wt3;
            out[B_ + 4 * b + (int)lane] = w;
        }

        if (!has_next) break;
#pragma unroll
        for (int k = 0; k < 8; k++) it[k] = nit[k];
        gid = ngid; iid = niid; b = bn;
    }
}

extern "C" void kernel_launch(void* const* d_in, const int* in_sizes, int n_in,
                              void* d_out, int out_size) {
    cudaFuncSetAttribute(agree_kernel, cudaFuncAttributeMaxDynamicSharedMemorySize, SMEM_BYTES);
    agree_kernel<<<GRID, TPB, SMEM_BYTES>>>(
        (const int*)d_in[0], (const int*)d_in[1], (const int*)d_in[2],
        (const float*)d_in[3], (const float*)d_in[4], (const float*)d_in[5],
        (const float*)d_in[6], (const float*)d_in[7], (const float*)d_in[8], (const float*)d_in[9],
        (const float*)d_in[10], (const float*)d_in[11], (const float*)d_in[12], (const float*)d_in[13],
        (const float*)d_in[14], (const float*)d_in[15],
        (float*)d_out);
}

// round 7
// speedup vs baseline: 1.4367x; 1.0473x over previous
#include <cuda_runtime.h>

// ---------------- problem constants ----------------
constexpr int B_  = 65536;
constexpr int D_  = 256;
constexpr int W1ROWS = 512, F1 = 16, W1PAD = 18;  // fp32, LDS.64: 9-word stride, gcd(9,16)=1 -> conflict-free
constexpr int P1ROWS = 768;                       // bf16x2: 4 words (16B) per row, LDS.128, conflict-free

constexpr int TPB  = 256;           // 8 warps / block
constexpr int WPB  = TPB / 32;
constexpr int GRID = 296;           // 2 blocks/SM -> 16 warps/SM

// dynamic shared layout (word offsets; word = 4B)
constexpr int OFF_W1  = 0;                        // 512*18 = 9216 floats
constexpr int OFF_P1B = OFF_W1 + W1ROWS * W1PAD;  // 9216: 768 rows * 4 words (bf16x2)
constexpr int OFF_B1  = OFF_P1B + P1ROWS * 4;     // 12288
constexpr int OFF_W2  = OFF_B1 + 16;
constexpr int OFF_PB1 = OFF_W2 + 16;
constexpr int OFF_PW2 = OFF_PB1 + 8;
constexpr int OFF_SC  = OFF_PW2 + 8;
constexpr int SMEM_WORDS = OFF_SC + 8;            // 12344
constexpr int SMEM_BYTES = SMEM_WORDS * 4;        // ~48.2 KB; 2 blocks = 96.5KB/SM

// ---------------- packed f32x2 helpers ----------------
__device__ __forceinline__ unsigned long long splat2(float x) {
    unsigned long long r;
    asm("mov.b64 %0, {%1, %1};" : "=l"(r) : "f"(x));
    return r;
}
__device__ __forceinline__ unsigned long long pack2u(unsigned x, unsigned y) {
    unsigned long long r;
    asm("mov.b64 %0, {%1, %2};" : "=l"(r) : "r"(x), "r"(y));
    return r;
}
__device__ __forceinline__ void ffma2(unsigned long long& d, unsigned long long a, unsigned long long b) {
    asm("fma.rn.f32x2 %0, %1, %2, %0;" : "+l"(d) : "l"(a), "l"(b));
}
__device__ __forceinline__ float lo2(unsigned long long v) { return __uint_as_float((unsigned)v); }
__device__ __forceinline__ float hi2(unsigned long long v) { return __uint_as_float((unsigned)(v >> 32)); }

// bf16x2 word -> packed f32x2 (lo bf16 -> lo f32, hi bf16 -> hi f32)
__device__ __forceinline__ unsigned long long bf2f2(unsigned w) {
    return pack2u(w << 16, w & 0xffff0000u);
}
// fp32 pair -> bf16x2 word (f1 in high half, f0 in low half), round-to-nearest
__device__ __forceinline__ unsigned f2bf2(float f0, float f1) {
    unsigned r;
    asm("cvt.rn.bf16x2.f32 %0, %1, %2;" : "=r"(r) : "f"(f1), "f"(f0));
    return r;
}

// Distributed reduce over 8 values: lane holds p[0..7] partials; returns the
// full 32-lane sum for o=(lane>>2)&7, replicated on each 4-lane o-group.
__device__ __forceinline__ float dreduce8(float* p, unsigned lane) {
    const unsigned FULL = 0xffffffffu;
    const bool b4 = (lane & 16), b3 = (lane & 8), b2 = (lane & 4);
#pragma unroll
    for (int j = 0; j < 4; j++) {
        float send = b4 ? p[j] : p[j + 4];
        float r = __shfl_xor_sync(FULL, send, 16);
        p[j] = (b4 ? p[j + 4] : p[j]) + r;
    }
#pragma unroll
    for (int j = 0; j < 2; j++) {
        float send = b3 ? p[j] : p[j + 2];
        float r = __shfl_xor_sync(FULL, send, 8);
        p[j] = (b3 ? p[j + 2] : p[j]) + r;
    }
    {
        float send = b2 ? p[0] : p[1];
        float r = __shfl_xor_sync(FULL, send, 4);
        p[0] = (b2 ? p[1] : p[0]) + r;
    }
    p[0] += __shfl_xor_sync(FULL, p[0], 2);
    p[0] += __shfl_xor_sync(FULL, p[0], 1);
    return p[0];
}

// Sum across the 8 o-groups; input identical within each 4-lane o-group.
__device__ __forceinline__ float xsum3(float v) {
    v += __shfl_xor_sync(0xffffffffu, v, 4);
    v += __shfl_xor_sync(0xffffffffu, v, 8);
    v += __shfl_xor_sync(0xffffffffu, v, 16);
    return v;
}

__global__ __launch_bounds__(TPB, 2) void agree_kernel(
    const int*   __restrict__ group_inputs,
    const int*   __restrict__ item_inputs,
    const int*   __restrict__ group_members,
    const float* __restrict__ user_emb,
    const float* __restrict__ item_emb,
    const float* __restrict__ group_emb,
    const float* __restrict__ att_w1,
    const float* __restrict__ att_b1,
    const float* __restrict__ att_w2,
    const float* __restrict__ att_b2,
    const float* __restrict__ cls_w,
    const float* __restrict__ cls_b,
    const float* __restrict__ pred_w1,
    const float* __restrict__ pred_b1,
    const float* __restrict__ pred_w2,
    const float* __restrict__ pred_b2,
    float* __restrict__ out)
{
    extern __shared__ float sm[];
    float*    s_w1  = sm + OFF_W1;
    unsigned* s_p1b = reinterpret_cast<unsigned*>(sm + OFF_P1B);
    float*    s_b1  = sm + OFF_B1;
    float*    s_w2  = sm + OFF_W2;
    float*    s_pb1 = sm + OFF_PB1;
    float*    s_pw2 = sm + OFF_PW2;
    float*    s_sc  = sm + OFF_SC;

    const int tid = threadIdx.x;

    // stage att weights fp32 (padded rows, conflict-free LDS.64)
    for (int i = tid; i < W1ROWS * F1; i += TPB) s_w1[(i >> 4) * W1PAD + (i & 15)] = att_w1[i];
    // stage pred weights as bf16x2: word j of row e = (W[e][2j], W[e][2j+1])
    for (int i = tid; i < P1ROWS * 4; i += TPB) {
        const int e = i >> 2, j = i & 3;
        s_p1b[i] = f2bf2(pred_w1[e * 8 + 2 * j], pred_w1[e * 8 + 2 * j + 1]);
    }
    if (tid < 16) { s_b1[tid] = att_b1[tid]; s_w2[tid] = att_w2[tid]; }
    if (tid < 8)  { s_pb1[tid] = pred_b1[tid]; s_pw2[tid] = pred_w2[tid]; }
    if (tid == 0) {
        s_sc[0] = att_b2[0]; s_sc[1] = pred_b2[0];
        s_sc[2] = cls_w[0];  s_sc[3] = cls_w[1];
        s_sc[4] = cls_b[0];  s_sc[5] = cls_b[1];
    }
    __syncthreads();

    const unsigned lane = tid & 31;
    const int warp = tid >> 5;
    const int oidx = (int)((lane >> 2) & 7);
    const float b1v0 = s_b1[oidx],  b1v1 = s_b1[8 + oidx];
    const float w2v0 = s_w2[oidx],  w2v1 = s_w2[8 + oidx];
    const float pb1v = s_pb1[oidx], pw2v = s_pw2[oidx];
    const float attb2 = s_sc[0], predb2 = s_sc[1];
    const float clsd  = s_sc[3] - s_sc[2];
    const float clsbd = s_sc[5] - s_sc[4];

    const int stride = GRID * WPB;
    int b = blockIdx.x * WPB + warp;

    // ---- pipeline prologue: indices + member/item rows for first b ----
    int gid = group_inputs[b];
    int iid = item_inputs[b];
    int4 mi4 = *reinterpret_cast<const int4*>(group_members + (size_t)gid * 4);

    float m0[8], m1[8], m2[8], m3[8], it[8];
    {
        const float* u0 = user_emb + (size_t)mi4.x * D_ + lane;
        const float* u1 = user_emb + (size_t)mi4.y * D_ + lane;
        const float* u2 = user_emb + (size_t)mi4.z * D_ + lane;
        const float* u3 = user_emb + (size_t)mi4.w * D_ + lane;
        const float* ip = item_emb + (size_t)iid   * D_ + lane;
#pragma unroll
        for (int k = 0; k < 8; k++) {
            m0[k] = u0[32 * k]; m1[k] = u1[32 * k];
            m2[k] = u2[32 * k]; m3[k] = u3[32 * k];
            it[k] = ip[32 * k];
        }
    }

    while (true) {
        // group-row load issued early (latency covered by attention phase)
        const float* gep = group_emb + (size_t)gid * D_ + lane;
        float ge[8];
#pragma unroll
        for (int k = 0; k < 8; k++) ge[k] = gep[32 * k];

        // prefetch next-b index chain (overlaps attention FFMA phase)
        const int bn = b + stride;
        const bool has_next = (bn < B_);
        int ngid = 0, niid = 0;
        int4 nmi4 = make_int4(0, 0, 0, 0);
        if (has_next) {
            ngid = group_inputs[bn];
            niid = item_inputs[bn];
            nmi4 = *reinterpret_cast<const int4*>(group_members + (size_t)ngid * 4);
        }

        // ---- attention MLP in two feature halves (f = 8H + [0,8)) ----
        float lp0 = 0.f, lp1 = 0.f, lp2 = 0.f, lp3 = 0.f;
#pragma unroll
        for (int H = 0; H < 2; H++) {
            unsigned long long a0[4], a1[4], a2[4], a3[4], ia[4];
#pragma unroll
            for (int fp = 0; fp < 4; fp++) { a0[fp] = 0; a1[fp] = 0; a2[fp] = 0; a3[fp] = 0; ia[fp] = 0; }
#pragma unroll
            for (int k = 0; k < 8; k++) {
                const int e = (int)lane + 32 * k;
                const float* wr  = s_w1 + e * W1PAD + 8 * H;   // member half rows [0,256)
                const float* wr2 = wr + 256 * W1PAD;           // item half rows [256,512)
                const unsigned long long v0 = splat2(m0[k]);
                const unsigned long long v1 = splat2(m1[k]);
                const unsigned long long v2 = splat2(m2[k]);
                const unsigned long long v3 = splat2(m3[k]);
                const unsigned long long vi = splat2(it[k]);
#pragma unroll
                for (int fp = 0; fp < 4; fp++) {
                    const unsigned long long w = *reinterpret_cast<const unsigned long long*>(wr + 2 * fp);
                    ffma2(a0[fp], v0, w);
                    ffma2(a1[fp], v1, w);
                    ffma2(a2[fp], v2, w);
                    ffma2(a3[fp], v3, w);
                    const unsigned long long wI = *reinterpret_cast<const unsigned long long*>(wr2 + 2 * fp);
                    ffma2(ia[fp], vi, wI);
                }
            }
            const float b1v = H ? b1v1 : b1v0;
            const float w2v = H ? w2v1 : w2v0;
#pragma unroll
            for (int s = 0; s < 4; s++) {
                const unsigned long long* a = (s == 0) ? a0 : (s == 1) ? a1 : (s == 2) ? a2 : a3;
                float p[8];
#pragma unroll
                for (int fp = 0; fp < 4; fp++) {
                    p[2 * fp]     = lo2(a[fp]) + lo2(ia[fp]);
                    p[2 * fp + 1] = hi2(a[fp]) + hi2(ia[fp]);
                }
                const float hs = dreduce8(p, lane);
                const float h = fmaxf(hs + b1v, 0.0f);
                const float c = h * w2v;
                if      (s == 0) lp0 += c;
                else if (s == 1) lp1 += c;
                else if (s == 2) lp2 += c;
                else             lp3 += c;
            }
        }
        float logits[4];
        logits[0] = xsum3(lp0) + attb2;
        logits[1] = xsum3(lp1) + attb2;
        logits[2] = xsum3(lp2) + attb2;
        logits[3] = xsum3(lp3) + attb2;

        // softmax + first-argmax (strict > matches jnp.argmax tie rule)
        float mx = logits[0]; int mi = 0;
#pragma unroll
        for (int s = 1; s < 4; s++) if (logits[s] > mx) { mx = logits[s]; mi = s; }
        const float e0 = __expf(logits[0] - mx), e1 = __expf(logits[1] - mx);
        const float e2 = __expf(logits[2] - mx), e3 = __expf(logits[3] - mx);
        const float inv = 1.0f / (e0 + e1 + e2 + e3);
        const float wt0 = e0 * inv, wt1 = e1 * inv, wt2 = e2 * inv, wt3 = e3 * inv;
        const float wmx = (mi == 0) ? wt0 : (mi == 1) ? wt1 : (mi == 2) ? wt2 : wt3;
        const bool pc = (wmx * clsd + clsbd) > 0.0f;

        // g = (leader | weighted) + group_emb  (last use of m0..m3)
        float g[8];
#pragma unroll
        for (int k = 0; k < 8; k++) {
            const float ws = wt0 * m0[k] + wt1 * m1[k] + wt2 * m2[k] + wt3 * m3[k];
            const float ld = (mi == 0) ? m0[k] : (mi == 1) ? m1[k] : (mi == 2) ? m2[k] : m3[k];
            g[k] = (pc ? ld : ws) + ge[k];
        }

        // ---- issue next-b row loads NOW (m regs dead; overlaps pred MLP) ----
        float nit[8];
        if (has_next) {
            const float* u0 = user_emb + (size_t)nmi4.x * D_ + lane;
            const float* u1 = user_emb + (size_t)nmi4.y * D_ + lane;
            const float* u2 = user_emb + (size_t)nmi4.z * D_ + lane;
            const float* u3 = user_emb + (size_t)nmi4.w * D_ + lane;
            const float* ip = item_emb + (size_t)niid   * D_ + lane;
#pragma unroll
            for (int k = 0; k < 8; k++) {
                m0[k] = u0[32 * k]; m1[k] = u1[32 * k];
                m2[k] = u2[32 * k]; m3[k] = u3[32 * k];
                nit[k] = ip[32 * k];
            }
        }

        // ---- prediction MLP (bf16 weights): sigmoid(relu([g*it,g,it]@W + b1)@w2 + b2) ----
        unsigned long long pa[4] = {0, 0, 0, 0};
#pragma unroll
        for (int k = 0; k < 8; k++) {
            const int e = (int)lane + 32 * k;
            // one LDS.128 per segment: 4 bf16x2 words = 8 weights (f=0..7)
            const uint4 qe = *reinterpret_cast<const uint4*>(s_p1b + 4 * e);             // elem rows
            const uint4 qg = *reinterpret_cast<const uint4*>(s_p1b + 4 * (e + 256));     // g rows
            const uint4 qi = *reinterpret_cast<const uint4*>(s_p1b + 4 * (e + 512));     // item rows
            const unsigned long long ve = splat2(g[k] * it[k]);
            const unsigned long long vg = splat2(g[k]);
            const unsigned long long vi = splat2(it[k]);
            ffma2(pa[0], ve, bf2f2(qe.x)); ffma2(pa[1], ve, bf2f2(qe.y));
            ffma2(pa[2], ve, bf2f2(qe.z)); ffma2(pa[3], ve, bf2f2(qe.w));
            ffma2(pa[0], vg, bf2f2(qg.x)); ffma2(pa[1], vg, bf2f2(qg.y));
            ffma2(pa[2], vg, bf2f2(qg.z)); ffma2(pa[3], vg, bf2f2(qg.w));
            ffma2(pa[0], vi, bf2f2(qi.x)); ffma2(pa[1], vi, bf2f2(qi.y));
            ffma2(pa[2], vi, bf2f2(qi.z)); ffma2(pa[3], vi, bf2f2(qi.w));
        }
        float q[8];
#pragma unroll
        for (int op = 0; op < 4; op++) { q[2 * op] = lo2(pa[op]); q[2 * op + 1] = hi2(pa[op]); }
        const float ps = dreduce8(q, lane);
        const float h2 = fmaxf(ps + pb1v, 0.0f);
        const float z = xsum3(h2 * pw2v) + predb2;
        const float y = 1.0f / (1.0f + __expf(-z));

        if (lane == 0) {
            out[b] = y;
            out[5 * B_ + b] = pc ? 1.0f : 0.0f;
        }
        if (lane < 4) {
            const float w = (lane == 0) ? wt0 : (lane == 1) ? wt1 : (lane == 2) ? wt2 : wt3;
            out[B_ + 4 * b + (int)lane] = w;
        }

        if (!has_next) break;
#pragma unroll
        for (int k = 0; k < 8; k++) it[k] = nit[k];
        gid = ngid; iid = niid; b = bn;
    }
}

extern "C" void kernel_launch(void* const* d_in, const int* in_sizes, int n_in,
                              void* d_out, int out_size) {
    cudaFuncSetAttribute(agree_kernel, cudaFuncAttributeMaxDynamicSharedMemorySize, SMEM_BYTES);
    agree_kernel<<<GRID, TPB, SMEM_BYTES>>>(
        (const int*)d_in[0], (const int*)d_in[1], (const int*)d_in[2],
        (const float*)d_in[3], (const float*)d_in[4], (const float*)d_in[5],
        (const float*)d_in[6], (const float*)d_in[7], (const float*)d_in[8], (const float*)d_in[9],
        (const float*)d_in[10], (const float*)d_in[11], (const float*)d_in[12], (const float*)d_in[13],
        (const float*)d_in[14], (const float*)d_in[15],
        (float*)d_out);
}

// round 8
// speedup vs baseline: 1.4770x; 1.0280x over previous
#include <cuda_runtime.h>

// ---------------- problem constants ----------------
constexpr int B_  = 65536;
constexpr int D_  = 256;
constexpr int W1ROWS = 512;         // att_w1 rows; bf16x2: 8 words used, padded to 12 (3x16B units, gcd(3,8)=1)
constexpr int W1PADW = 12;
constexpr int P1ROWS = 768;         // pred_w1: bf16x2, 4 words (16B) per row

constexpr int TPB  = 256;           // 8 warps / block
constexpr int WPB  = TPB / 32;
constexpr int GRID = 296;           // 2 blocks/SM -> 16 warps/SM

// dynamic shared layout (word offsets)
constexpr int OFF_W1B = 0;                         // 512*12 = 6144 words
constexpr int OFF_P1B = OFF_W1B + W1ROWS * W1PADW; // 6144
constexpr int OFF_B1  = OFF_P1B + P1ROWS * 4;      // 9216
constexpr int OFF_W2  = OFF_B1 + 16;
constexpr int OFF_PB1 = OFF_W2 + 16;
constexpr int OFF_PW2 = OFF_PB1 + 8;
constexpr int OFF_SC  = OFF_PW2 + 8;
constexpr int SMEM_WORDS = OFF_SC + 8;             // 9272
constexpr int SMEM_BYTES = SMEM_WORDS * 4;         // ~36.2 KB; 2 blocks = 72.5KB/SM

// ---------------- packed f32x2 helpers ----------------
__device__ __forceinline__ unsigned long long splat2(float x) {
    unsigned long long r;
    asm("mov.b64 %0, {%1, %1};" : "=l"(r) : "f"(x));
    return r;
}
__device__ __forceinline__ unsigned long long pack2u(unsigned x, unsigned y) {
    unsigned long long r;
    asm("mov.b64 %0, {%1, %2};" : "=l"(r) : "r"(x), "r"(y));
    return r;
}
__device__ __forceinline__ void ffma2(unsigned long long& d, unsigned long long a, unsigned long long b) {
    asm("fma.rn.f32x2 %0, %1, %2, %0;" : "+l"(d) : "l"(a), "l"(b));
}
__device__ __forceinline__ float lo2(unsigned long long v) { return __uint_as_float((unsigned)v); }
__device__ __forceinline__ float hi2(unsigned long long v) { return __uint_as_float((unsigned)(v >> 32)); }

// bf16x2 word -> packed f32x2 (lo bf16 -> lo f32, hi bf16 -> hi f32)
__device__ __forceinline__ unsigned long long bf2f2(unsigned w) {
    return pack2u(w << 16, w & 0xffff0000u);
}
// fp32 pair -> bf16x2 word (f0 low half, f1 high half), round-to-nearest
__device__ __forceinline__ unsigned f2bf2(float f0, float f1) {
    unsigned r;
    asm("cvt.rn.bf16x2.f32 %0, %1, %2;" : "=r"(r) : "f"(f1), "f"(f0));
    return r;
}

// Distributed reduce over 8 values: lane holds p[0..7] partials; returns the
// full 32-lane sum for o=(lane>>2)&7, replicated on each 4-lane o-group.
__device__ __forceinline__ float dreduce8(float* p, unsigned lane) {
    const unsigned FULL = 0xffffffffu;
    const bool b4 = (lane & 16), b3 = (lane & 8), b2 = (lane & 4);
#pragma unroll
    for (int j = 0; j < 4; j++) {
        float send = b4 ? p[j] : p[j + 4];
        float r = __shfl_xor_sync(FULL, send, 16);
        p[j] = (b4 ? p[j + 4] : p[j]) + r;
    }
#pragma unroll
    for (int j = 0; j < 2; j++) {
        float send = b3 ? p[j] : p[j + 2];
        float r = __shfl_xor_sync(FULL, send, 8);
        p[j] = (b3 ? p[j + 2] : p[j]) + r;
    }
    {
        float send = b2 ? p[0] : p[1];
        float r = __shfl_xor_sync(FULL, send, 4);
        p[0] = (b2 ? p[1] : p[0]) + r;
    }
    p[0] += __shfl_xor_sync(FULL, p[0], 2);
    p[0] += __shfl_xor_sync(FULL, p[0], 1);
    return p[0];
}

// Sum across the 8 o-groups; input identical within each 4-lane o-group.
__device__ __forceinline__ float xsum3(float v) {
    v += __shfl_xor_sync(0xffffffffu, v, 4);
    v += __shfl_xor_sync(0xffffffffu, v, 8);
    v += __shfl_xor_sync(0xffffffffu, v, 16);
    return v;
}

__global__ __launch_bounds__(TPB, 2) void agree_kernel(
    const int*   __restrict__ group_inputs,
    const int*   __restrict__ item_inputs,
    const int*   __restrict__ group_members,
    const float* __restrict__ user_emb,
    const float* __restrict__ item_emb,
    const float* __restrict__ group_emb,
    const float* __restrict__ att_w1,
    const float* __restrict__ att_b1,
    const float* __restrict__ att_w2,
    const float* __restrict__ att_b2,
    const float* __restrict__ cls_w,
    const float* __restrict__ cls_b,
    const float* __restrict__ pred_w1,
    const float* __restrict__ pred_b1,
    const float* __restrict__ pred_w2,
    const float* __restrict__ pred_b2,
    float* __restrict__ out)
{
    extern __shared__ float sm[];
    unsigned* s_w1b = reinterpret_cast<unsigned*>(sm + OFF_W1B);
    unsigned* s_p1b = reinterpret_cast<unsigned*>(sm + OFF_P1B);
    float*    s_b1  = sm + OFF_B1;
    float*    s_w2  = sm + OFF_W2;
    float*    s_pb1 = sm + OFF_PB1;
    float*    s_pw2 = sm + OFF_PW2;
    float*    s_sc  = sm + OFF_SC;

    const int tid = threadIdx.x;

    // stage att weights as bf16x2: word j of row e = (W[e][2j], W[e][2j+1]), rows padded 8->12 words
    for (int i = tid; i < W1ROWS * 8; i += TPB) {
        const int e = i >> 3, j = i & 7;
        s_w1b[e * W1PADW + j] = f2bf2(att_w1[e * 16 + 2 * j], att_w1[e * 16 + 2 * j + 1]);
    }
    // stage pred weights as bf16x2 (4 words per row, dense)
    for (int i = tid; i < P1ROWS * 4; i += TPB) {
        const int e = i >> 2, j = i & 3;
        s_p1b[i] = f2bf2(pred_w1[e * 8 + 2 * j], pred_w1[e * 8 + 2 * j + 1]);
    }
    if (tid < 16) { s_b1[tid] = att_b1[tid]; s_w2[tid] = att_w2[tid]; }
    if (tid < 8)  { s_pb1[tid] = pred_b1[tid]; s_pw2[tid] = pred_w2[tid]; }
    if (tid == 0) {
        s_sc[0] = att_b2[0]; s_sc[1] = pred_b2[0];
        s_sc[2] = cls_w[0];  s_sc[3] = cls_w[1];
        s_sc[4] = cls_b[0];  s_sc[5] = cls_b[1];
    }
    __syncthreads();

    const unsigned lane = tid & 31;
    const int warp = tid >> 5;
    const int oidx = (int)((lane >> 2) & 7);
    const float b1v0 = s_b1[oidx],  b1v1 = s_b1[8 + oidx];
    const float w2v0 = s_w2[oidx],  w2v1 = s_w2[8 + oidx];
    const float pb1v = s_pb1[oidx], pw2v = s_pw2[oidx];
    const float attb2 = s_sc[0], predb2 = s_sc[1];
    const float clsd  = s_sc[3] - s_sc[2];
    const float clsbd = s_sc[5] - s_sc[4];

    const int stride = GRID * WPB;
    int b = blockIdx.x * WPB + warp;

    // ---- pipeline prologue: indices + member/item rows for first b ----
    int gid = group_inputs[b];
    int iid = item_inputs[b];
    int4 mi4 = *reinterpret_cast<const int4*>(group_members + (size_t)gid * 4);

    float m0[8], m1[8], m2[8], m3[8], it[8];
    {
        const float* u0 = user_emb + (size_t)mi4.x * D_ + lane;
        const float* u1 = user_emb + (size_t)mi4.y * D_ + lane;
        const float* u2 = user_emb + (size_t)mi4.z * D_ + lane;
        const float* u3 = user_emb + (size_t)mi4.w * D_ + lane;
        const float* ip = item_emb + (size_t)iid   * D_ + lane;
#pragma unroll
        for (int k = 0; k < 8; k++) {
            m0[k] = u0[32 * k]; m1[k] = u1[32 * k];
            m2[k] = u2[32 * k]; m3[k] = u3[32 * k];
            it[k] = ip[32 * k];
        }
    }

    while (true) {
        // group-row load issued early (latency covered by attention phase)
        const float* gep = group_emb + (size_t)gid * D_ + lane;
        float ge[8];
#pragma unroll
        for (int k = 0; k < 8; k++) ge[k] = gep[32 * k];

        // prefetch next-b index chain (overlaps attention FFMA phase)
        const int bn = b + stride;
        const bool has_next = (bn < B_);
        int ngid = 0, niid = 0;
        int4 nmi4 = make_int4(0, 0, 0, 0);
        if (has_next) {
            ngid = group_inputs[bn];
            niid = item_inputs[bn];
            nmi4 = *reinterpret_cast<const int4*>(group_members + (size_t)ngid * 4);
        }

        // ---- attention MLP (bf16 weights) in two feature halves ----
        float lp0 = 0.f, lp1 = 0.f, lp2 = 0.f, lp3 = 0.f;
#pragma unroll
        for (int H = 0; H < 2; H++) {
            unsigned long long a0[4], a1[4], a2[4], a3[4], ia[4];
#pragma unroll
            for (int fp = 0; fp < 4; fp++) { a0[fp] = 0; a1[fp] = 0; a2[fp] = 0; a3[fp] = 0; ia[fp] = 0; }
#pragma unroll
            for (int k = 0; k < 8; k++) {
                const int e = (int)lane + 32 * k;
                // one LDS.128 per half per operand: 4 bf16x2 words = 8 features
                const uint4 qm = *reinterpret_cast<const uint4*>(s_w1b + e * W1PADW + 4 * H);
                const uint4 qI = *reinterpret_cast<const uint4*>(s_w1b + (e + 256) * W1PADW + 4 * H);
                const unsigned long long v0 = splat2(m0[k]);
                const unsigned long long v1 = splat2(m1[k]);
                const unsigned long long v2 = splat2(m2[k]);
                const unsigned long long v3 = splat2(m3[k]);
                const unsigned long long vi = splat2(it[k]);
                const unsigned long long w0 = bf2f2(qm.x), w1 = bf2f2(qm.y);
                const unsigned long long w2 = bf2f2(qm.z), w3 = bf2f2(qm.w);
                ffma2(a0[0], v0, w0); ffma2(a0[1], v0, w1); ffma2(a0[2], v0, w2); ffma2(a0[3], v0, w3);
                ffma2(a1[0], v1, w0); ffma2(a1[1], v1, w1); ffma2(a1[2], v1, w2); ffma2(a1[3], v1, w3);
                ffma2(a2[0], v2, w0); ffma2(a2[1], v2, w1); ffma2(a2[2], v2, w2); ffma2(a2[3], v2, w3);
                ffma2(a3[0], v3, w0); ffma2(a3[1], v3, w1); ffma2(a3[2], v3, w2); ffma2(a3[3], v3, w3);
                ffma2(ia[0], vi, bf2f2(qI.x)); ffma2(ia[1], vi, bf2f2(qI.y));
                ffma2(ia[2], vi, bf2f2(qI.z)); ffma2(ia[3], vi, bf2f2(qI.w));
            }
            const float b1v = H ? b1v1 : b1v0;
            const float w2v = H ? w2v1 : w2v0;
#pragma unroll
            for (int s = 0; s < 4; s++) {
                const unsigned long long* a = (s == 0) ? a0 : (s == 1) ? a1 : (s == 2) ? a2 : a3;
                float p[8];
#pragma unroll
                for (int fp = 0; fp < 4; fp++) {
                    p[2 * fp]     = lo2(a[fp]) + lo2(ia[fp]);
                    p[2 * fp + 1] = hi2(a[fp]) + hi2(ia[fp]);
                }
                const float hs = dreduce8(p, lane);
                const float h = fmaxf(hs + b1v, 0.0f);
                const float c = h * w2v;
                if      (s == 0) lp0 += c;
                else if (s == 1) lp1 += c;
                else if (s == 2) lp2 += c;
                else             lp3 += c;
            }
        }
        float logits[4];
        logits[0] = xsum3(lp0) + attb2;
        logits[1] = xsum3(lp1) + attb2;
        logits[2] = xsum3(lp2) + attb2;
        logits[3] = xsum3(lp3) + attb2;

        // softmax + first-argmax (strict > matches jnp.argmax tie rule)
        float mx = logits[0]; int mi = 0;
#pragma unroll
        for (int s = 1; s < 4; s++) if (logits[s] > mx) { mx = logits[s]; mi = s; }
        const float e0 = __expf(logits[0] - mx), e1 = __expf(logits[1] - mx);
        const float e2 = __expf(logits[2] - mx), e3 = __expf(logits[3] - mx);
        const float inv = 1.0f / (e0 + e1 + e2 + e3);
        const float wt0 = e0 * inv, wt1 = e1 * inv, wt2 = e2 * inv, wt3 = e3 * inv;
        const float wmx = (mi == 0) ? wt0 : (mi == 1) ? wt1 : (mi == 2) ? wt2 : wt3;
        const bool pc = (wmx * clsd + clsbd) > 0.0f;

        // g = (leader | weighted) + group_emb  (last use of m0..m3)
        float g[8];
#pragma unroll
        for (int k = 0; k < 8; k++) {
            const float ws = wt0 * m0[k] + wt1 * m1[k] + wt2 * m2[k] + wt3 * m3[k];
            const float ld = (mi == 0) ? m0[k] : (mi == 1) ? m1[k] : (mi == 2) ? m2[k] : m3[k];
            g[k] = (pc ? ld : ws) + ge[k];
        }

        // ---- issue next-b row loads NOW (m regs dead; overlaps pred MLP) ----
        float nit[8];
        if (has_next) {
            const float* u0 = user_emb + (size_t)nmi4.x * D_ + lane;
            const float* u1 = user_emb + (size_t)nmi4.y * D_ + lane;
            const float* u2 = user_emb + (size_t)nmi4.z * D_ + lane;
            const float* u3 = user_emb + (size_t)nmi4.w * D_ + lane;
            const float* ip = item_emb + (size_t)niid   * D_ + lane;
#pragma unroll
            for (int k = 0; k < 8; k++) {
                m0[k] = u0[32 * k]; m1[k] = u1[32 * k];
                m2[k] = u2[32 * k]; m3[k] = u3[32 * k];
                nit[k] = ip[32 * k];
            }
        }

        // ---- prediction MLP (bf16 weights): sigmoid(relu([g*it,g,it]@W + b1)@w2 + b2) ----
        unsigned long long pa[4] = {0, 0, 0, 0};
#pragma unroll
        for (int k = 0; k < 8; k++) {
            const int e = (int)lane + 32 * k;
            const uint4 qe = *reinterpret_cast<const uint4*>(s_p1b + 4 * e);
            const uint4 qg = *reinterpret_cast<const uint4*>(s_p1b + 4 * (e + 256));
            const uint4 qi = *reinterpret_cast<const uint4*>(s_p1b + 4 * (e + 512));
            const unsigned long long ve = splat2(g[k] * it[k]);
            const unsigned long long vg = splat2(g[k]);
            const unsigned long long vi = splat2(it[k]);
            ffma2(pa[0], ve, bf2f2(qe.x)); ffma2(pa[1], ve, bf2f2(qe.y));
            ffma2(pa[2], ve, bf2f2(qe.z)); ffma2(pa[3], ve, bf2f2(qe.w));
            ffma2(pa[0], vg, bf2f2(qg.x)); ffma2(pa[1], vg, bf2f2(qg.y));
            ffma2(pa[2], vg, bf2f2(qg.z)); ffma2(pa[3], vg, bf2f2(qg.w));
            ffma2(pa[0], vi, bf2f2(qi.x)); ffma2(pa[1], vi, bf2f2(qi.y));
            ffma2(pa[2], vi, bf2f2(qi.z)); ffma2(pa[3], vi, bf2f2(qi.w));
        }
        float q[8];
#pragma unroll
        for (int op = 0; op < 4; op++) { q[2 * op] = lo2(pa[op]); q[2 * op + 1] = hi2(pa[op]); }
        const float ps = dreduce8(q, lane);
        const float h2 = fmaxf(ps + pb1v, 0.0f);
        const float z = xsum3(h2 * pw2v) + predb2;
        const float y = 1.0f / (1.0f + __expf(-z));

        if (lane == 0) {
            out[b] = y;
            out[5 * B_ + b] = pc ? 1.0f : 0.0f;
        }
        if (lane < 4) {
            const float w = (lane == 0) ? wt0 : (lane == 1) ? wt1 : (lane == 2) ? wt2 : wt3;
            out[B_ + 4 * b + (int)lane] = w;
        }

        if (!has_next) break;
#pragma unroll
        for (int k = 0; k < 8; k++) it[k] = nit[k];
        gid = ngid; iid = niid; b = bn;
    }
}

extern "C" void kernel_launch(void* const* d_in, const int* in_sizes, int n_in,
                              void* d_out, int out_size) {
    cudaFuncSetAttribute(agree_kernel, cudaFuncAttributeMaxDynamicSharedMemorySize, SMEM_BYTES);
    agree_kernel<<<GRID, TPB, SMEM_BYTES>>>(
        (const int*)d_in[0], (const int*)d_in[1], (const int*)d_in[2],
        (const float*)d_in[3], (const float*)d_in[4], (const float*)d_in[5],
        (const float*)d_in[6], (const float*)d_in[7], (const float*)d_in[8], (const float*)d_in[9],
        (const float*)d_in[10], (const float*)d_in[11], (const float*)d_in[12], (const float*)d_in[13],
        (const float*)d_in[14], (const float*)d_in[15],
        (float*)d_out);
}